// round 2
// baseline (speedup 1.0000x reference)
#include <cuda_runtime.h>
#include <cuda_bf16.h>
#include <cstdint>

#define N_NODES 100000
#define E_EDGES 1600000
#define IN_CH   128
#define HEADS   4
#define OUT_CH  32
#define OC      (HEADS * OUT_CH)   // 128
#define NEG_SLOPE 0.2f

// ---------------- scratch (device globals; no allocation allowed) ----------
__device__ __align__(16) float    g_h[(size_t)N_NODES * OC];        // 51.2 MB
__device__ __align__(16) float    g_ssrc[N_NODES * HEADS];
__device__ __align__(16) float    g_sdst[N_NODES * HEADS];
__device__ __align__(16) unsigned g_segmax[N_NODES * HEADS];        // order-encoded
__device__ __align__(16) float    g_segsum[N_NODES * HEADS];
__device__ __align__(16) float    g_rnorm[N_NODES * HEADS];
__device__ __align__(16) float    g_expal[(size_t)E_EDGES * HEADS]; // 25.6 MB
__device__ int g_is64;

// order-preserving float<->uint encode for atomicMax on signed floats
__device__ __forceinline__ unsigned fenc(float f) {
    unsigned u = __float_as_uint(f);
    return (u & 0x80000000u) ? ~u : (u | 0x80000000u);
}
__device__ __forceinline__ float fdec(unsigned u) {
    return (u & 0x80000000u) ? __uint_as_float(u ^ 0x80000000u)
                             : __uint_as_float(~u);
}

__device__ __forceinline__ void red_add_v4(float* p, float4 v) {
    asm volatile("red.global.add.v4.f32 [%0], {%1, %2, %3, %4};"
                 :: "l"(p), "f"(v.x), "f"(v.y), "f"(v.z), "f"(v.w)
                 : "memory");
}

// runtime-dtype edge load (src, dst) for edge e
__device__ __forceinline__ void load_edge(const void* ei, int e, int& src, int& dst) {
    if (g_is64) {
        const long long* p = (const long long*)ei;
        src = (int)p[e];
        dst = (int)p[E_EDGES + e];
    } else {
        const int* p = (const int*)ei;
        src = p[e];
        dst = p[E_EDGES + e];
    }
}

// ---------------- K0: detect edge_index dtype -------------------------------
// int64 little-endian with values < 2^31 -> every odd 32-bit word is zero.
__global__ void k_detect(const unsigned* __restrict__ ei32) {
    if (threadIdx.x != 0 || blockIdx.x != 0) return;
    int allzero = 1;
    #pragma unroll 1
    for (int i = 0; i < 64; i++) {
        if (ei32[2 * i + 1] != 0u) { allzero = 0; break; }
    }
    g_is64 = allzero;
}

// ---------------- K1: h = x @ W  (fp32, smem x-tile, reg-blocked) ----------
__global__ void __launch_bounds__(128) k_gemm(const float* __restrict__ x,
                                              const float* __restrict__ W) {
    __shared__ float xs[32][IN_CH];                    // 16 KB
    const int nbase = blockIdx.x * 32;
    const int t = threadIdx.x;

    #pragma unroll
    for (int i = t; i < 32 * IN_CH; i += 128) {
        int node = i >> 7, k = i & 127;
        xs[node][k] = x[(size_t)(nbase + node) * IN_CH + k];
    }
    __syncthreads();

    const int c0 = (t & 31) * 4;
    const int j0 = (t >> 5) * 8;

    float4 acc[8];
    #pragma unroll
    for (int j = 0; j < 8; j++) acc[j] = make_float4(0.f, 0.f, 0.f, 0.f);

    #pragma unroll 4
    for (int k = 0; k < IN_CH; k++) {
        const float4 w4 = __ldg((const float4*)(W + (size_t)k * OC + c0));
        #pragma unroll
        for (int j = 0; j < 8; j++) {
            const float xv = xs[j0 + j][k];
            acc[j].x = fmaf(xv, w4.x, acc[j].x);
            acc[j].y = fmaf(xv, w4.y, acc[j].y);
            acc[j].z = fmaf(xv, w4.z, acc[j].z);
            acc[j].w = fmaf(xv, w4.w, acc[j].w);
        }
    }
    #pragma unroll
    for (int j = 0; j < 8; j++)
        *(float4*)(g_h + (size_t)(nbase + j0 + j) * OC + c0) = acc[j];
}

// ---------------- K2: per-(node,head) attention scalars + init -------------
__global__ void k_scores_init(const float* __restrict__ att) {
    const int i = blockIdx.x * blockDim.x + threadIdx.x;   // node*4 + head
    if (i >= N_NODES * HEADS) return;
    const int node = i >> 2, head = i & 3;
    const float* hp = g_h + (size_t)node * OC + head * OUT_CH;
    const float* as = att + head * 2 * OUT_CH;
    const float* ad = as + OUT_CH;
    float ss = 0.f, sd = 0.f;
    #pragma unroll
    for (int c = 0; c < OUT_CH; c++) {
        const float v = hp[c];
        ss = fmaf(v, __ldg(as + c), ss);
        sd = fmaf(v, __ldg(ad + c), sd);
    }
    g_ssrc[i] = ss;
    g_sdst[i] = sd;
    g_segmax[i] = fenc(-__int_as_float(0x7f800000));  // enc(-inf)
    g_segsum[i] = 0.f;
}

// ---------------- K3: out = bias ----------------
__global__ void k_out_init(const float* __restrict__ bias, float* __restrict__ out) {
    const size_t i = (size_t)blockIdx.x * blockDim.x + threadIdx.x;
    if (i < (size_t)N_NODES * OC) out[i] = bias[i & (OC - 1)];
}

// ---------------- K4: per-edge segment max ----------------
__global__ void k_edge_max(const void* __restrict__ ei) {
    const int e = blockIdx.x * blockDim.x + threadIdx.x;
    if (e >= E_EDGES) return;
    int src, dst;
    load_edge(ei, e, src, dst);
    const float4 a = *(const float4*)(g_ssrc + (size_t)src * 4);
    const float4 b = *(const float4*)(g_sdst + (size_t)dst * 4);
    float al[4] = {a.x + b.x, a.y + b.y, a.z + b.z, a.w + b.w};
    #pragma unroll
    for (int hh = 0; hh < 4; hh++) {
        float v = al[hh];
        v = (v >= 0.f) ? v : NEG_SLOPE * v;
        atomicMax(&g_segmax[(size_t)dst * 4 + hh], fenc(v));
    }
}

// ---------------- K5: per-edge exp + segment sum ----------------
__global__ void k_edge_exp(const void* __restrict__ ei) {
    const int e = blockIdx.x * blockDim.x + threadIdx.x;
    if (e >= E_EDGES) return;
    int src, dst;
    load_edge(ei, e, src, dst);
    const float4 a = *(const float4*)(g_ssrc + (size_t)src * 4);
    const float4 b = *(const float4*)(g_sdst + (size_t)dst * 4);
    const uint4 m = *(const uint4*)(g_segmax + (size_t)dst * 4);
    float al[4] = {a.x + b.x, a.y + b.y, a.z + b.z, a.w + b.w};
    const unsigned mm[4] = {m.x, m.y, m.z, m.w};
    float4 ex;
    float* exp_ = &ex.x;
    #pragma unroll
    for (int hh = 0; hh < 4; hh++) {
        float v = al[hh];
        v = (v >= 0.f) ? v : NEG_SLOPE * v;
        exp_[hh] = __expf(v - fdec(mm[hh]));
    }
    *(float4*)(g_expal + (size_t)e * 4) = ex;
    red_add_v4(g_segsum + (size_t)dst * 4, ex);
}

// ---------------- K6: reciprocal normalizer ----------------
__global__ void k_rnorm() {
    const int i = blockIdx.x * blockDim.x + threadIdx.x;
    if (i < N_NODES * HEADS) g_rnorm[i] = 1.f / (g_segsum[i] + 1e-16f);
}

// ---------------- K7: weighted scatter-aggregate (1 warp / edge) -----------
__global__ void __launch_bounds__(256) k_aggregate(const void* __restrict__ ei,
                                                   float* __restrict__ out) {
    const int gw = (blockIdx.x * blockDim.x + threadIdx.x) >> 5;
    if (gw >= E_EDGES) return;
    const int lane = threadIdx.x & 31;
    int src, dst;
    load_edge(ei, gw, src, dst);
    const int head = lane >> 3;
    const float coef = __ldg(g_expal + (size_t)gw * 4 + head) *
                       __ldg(g_rnorm + (size_t)dst * 4 + head);
    const float4 hv = *(const float4*)(g_h + (size_t)src * OC + lane * 4);
    float4 v = make_float4(hv.x * coef, hv.y * coef, hv.z * coef, hv.w * coef);
    red_add_v4(out + (size_t)dst * OC + lane * 4, v);
}

// ---------------- launch ----------------
extern "C" void kernel_launch(void* const* d_in, const int* in_sizes, int n_in,
                              void* d_out, int out_size) {
    const float* x    = (const float*)d_in[0];
    const void*  ei   = d_in[1];
    const float* W    = (const float*)d_in[2];
    const float* att  = (const float*)d_in[3];
    const float* bias = (const float*)d_in[4];
    float*       out  = (float*)d_out;

    (void)in_sizes; (void)n_in; (void)out_size;

    k_detect<<<1, 32>>>((const unsigned*)ei);
    k_gemm<<<N_NODES / 32, 128>>>(x, W);
    k_out_init<<<(N_NODES * OC + 255) / 256, 256>>>(bias, out);
    k_scores_init<<<(N_NODES * HEADS + 255) / 256, 256>>>(att);
    k_edge_max<<<(E_EDGES + 255) / 256, 256>>>(ei);
    k_edge_exp<<<(E_EDGES + 255) / 256, 256>>>(ei);
    k_rnorm<<<(N_NODES * HEADS + 255) / 256, 256>>>();
    k_aggregate<<<(E_EDGES * 32 + 255) / 256, 256>>>(ei, out);
}

// round 3
// speedup vs baseline: 1.1280x; 1.1280x over previous
#include <cuda_runtime.h>
#include <cuda_bf16.h>
#include <cstdint>

#define N_NODES 100000
#define E_EDGES 1600000
#define IN_CH   128
#define HEADS   4
#define OUT_CH  32
#define OC      (HEADS * OUT_CH)   // 128
#define NEG_SLOPE 0.2f

// ---------------- scratch (device globals; no allocation allowed) ----------
__device__ __align__(16) float    g_h[(size_t)N_NODES * OC];         // 51.2 MB
__device__ __align__(16) float    g_ssrc[N_NODES * HEADS];
__device__ __align__(16) float    g_sdst[N_NODES * HEADS];
__device__ __align__(16) unsigned g_segmax[N_NODES * HEADS];         // order-encoded
__device__ __align__(16) float    g_alpha[(size_t)E_EDGES * HEADS];  // 25.6 MB
__device__ __align__(16) float    g_csr_w[(size_t)E_EDGES * HEADS];  // 25.6 MB (sorted exp weights)
__device__ int g_csr_src[E_EDGES];                                   // 6.4 MB (sorted src ids)
__device__ int g_deg[N_NODES];
__device__ int g_off[N_NODES + 1];
__device__ int g_cursor[N_NODES];
__device__ int g_is64;

// order-preserving float<->uint encode for atomicMax on signed floats
__device__ __forceinline__ unsigned fenc(float f) {
    unsigned u = __float_as_uint(f);
    return (u & 0x80000000u) ? ~u : (u | 0x80000000u);
}
__device__ __forceinline__ float fdec(unsigned u) {
    return (u & 0x80000000u) ? __uint_as_float(u ^ 0x80000000u)
                             : __uint_as_float(~u);
}

// runtime-dtype edge load (src, dst) for edge e
__device__ __forceinline__ void load_edge(const void* ei, int e, int& src, int& dst) {
    if (g_is64) {
        const long long* p = (const long long*)ei;
        src = (int)p[e];
        dst = (int)p[E_EDGES + e];
    } else {
        const int* p = (const int*)ei;
        src = p[e];
        dst = p[E_EDGES + e];
    }
}

// ---------------- K0: detect edge_index dtype + zero deg -------------------
__global__ void k_detect(const unsigned* __restrict__ ei32) {
    if (threadIdx.x != 0 || blockIdx.x != 0) return;
    int allzero = 1;
    #pragma unroll 1
    for (int i = 0; i < 64; i++) {
        if (ei32[2 * i + 1] != 0u) { allzero = 0; break; }
    }
    g_is64 = allzero;
}

__global__ void k_init_deg() {
    const int i = blockIdx.x * blockDim.x + threadIdx.x;
    if (i < N_NODES) g_deg[i] = 0;
}

// ---------------- K1: h = x @ W + fused scores + segmax init ---------------
// block = 128 threads (4 warps), 32 nodes per block.
// warp w owns nodes j0=8w..8w+7; lane owns channels c0=lane*4..+3 (head=lane>>3).
__global__ void __launch_bounds__(128) k_gemm(const float* __restrict__ x,
                                              const float* __restrict__ W,
                                              const float* __restrict__ att) {
    __shared__ float xs[32][IN_CH];                    // 16 KB
    const int nbase = blockIdx.x * 32;
    const int t = threadIdx.x;

    #pragma unroll
    for (int i = t; i < 32 * IN_CH; i += 128) {
        int node = i >> 7, k = i & 127;
        xs[node][k] = x[(size_t)(nbase + node) * IN_CH + k];
    }
    __syncthreads();

    const int lane = t & 31;
    const int c0 = lane * 4;
    const int j0 = (t >> 5) * 8;
    const int head = lane >> 3;

    float4 acc[8];
    #pragma unroll
    for (int j = 0; j < 8; j++) acc[j] = make_float4(0.f, 0.f, 0.f, 0.f);

    #pragma unroll 4
    for (int k = 0; k < IN_CH; k++) {
        const float4 w4 = __ldg((const float4*)(W + (size_t)k * OC + c0));
        #pragma unroll
        for (int j = 0; j < 8; j++) {
            const float xv = xs[j0 + j][k];
            acc[j].x = fmaf(xv, w4.x, acc[j].x);
            acc[j].y = fmaf(xv, w4.y, acc[j].y);
            acc[j].z = fmaf(xv, w4.z, acc[j].z);
            acc[j].w = fmaf(xv, w4.w, acc[j].w);
        }
    }
    #pragma unroll
    for (int j = 0; j < 8; j++)
        *(float4*)(g_h + (size_t)(nbase + j0 + j) * OC + c0) = acc[j];

    // ---- fused attention scores: ss = <h, att_src>, sd = <h, att_dst> ----
    const int kloc = c0 & 31;  // channel offset within this head
    const float4 as4 = __ldg((const float4*)(att + head * 2 * OUT_CH + kloc));
    const float4 ad4 = __ldg((const float4*)(att + head * 2 * OUT_CH + OUT_CH + kloc));

    #pragma unroll
    for (int j = 0; j < 8; j++) {
        float ss = acc[j].x * as4.x + acc[j].y * as4.y + acc[j].z * as4.z + acc[j].w * as4.w;
        float sd = acc[j].x * ad4.x + acc[j].y * ad4.y + acc[j].z * ad4.z + acc[j].w * ad4.w;
        #pragma unroll
        for (int off = 4; off; off >>= 1) {
            ss += __shfl_xor_sync(0xffffffffu, ss, off);
            sd += __shfl_xor_sync(0xffffffffu, sd, off);
        }
        if ((lane & 7) == j) {
            const int idx = (nbase + j0 + j) * 4 + head;
            g_ssrc[idx] = ss;
            g_sdst[idx] = sd;
            g_segmax[idx] = fenc(-__int_as_float(0x7f800000));  // enc(-inf)
        }
    }
}

// ---------------- K2: per-edge alpha + segment max + degree histogram ------
__global__ void k_edge1(const void* __restrict__ ei) {
    const int e = blockIdx.x * blockDim.x + threadIdx.x;
    if (e >= E_EDGES) return;
    int src, dst;
    load_edge(ei, e, src, dst);
    const float4 a = *(const float4*)(g_ssrc + (size_t)src * 4);
    const float4 b = *(const float4*)(g_sdst + (size_t)dst * 4);
    float4 al;
    al.x = a.x + b.x; al.y = a.y + b.y; al.z = a.z + b.z; al.w = a.w + b.w;
    al.x = (al.x >= 0.f) ? al.x : NEG_SLOPE * al.x;
    al.y = (al.y >= 0.f) ? al.y : NEG_SLOPE * al.y;
    al.z = (al.z >= 0.f) ? al.z : NEG_SLOPE * al.z;
    al.w = (al.w >= 0.f) ? al.w : NEG_SLOPE * al.w;
    *(float4*)(g_alpha + (size_t)e * 4) = al;
    atomicMax(&g_segmax[(size_t)dst * 4 + 0], fenc(al.x));
    atomicMax(&g_segmax[(size_t)dst * 4 + 1], fenc(al.y));
    atomicMax(&g_segmax[(size_t)dst * 4 + 2], fenc(al.z));
    atomicMax(&g_segmax[(size_t)dst * 4 + 3], fenc(al.w));
    atomicAdd(&g_deg[dst], 1);
}

// ---------------- K3: exclusive prefix scan of degrees (1 block) -----------
__global__ void __launch_bounds__(1024) k_scan() {
    __shared__ int sm[1024];
    const int t = threadIdx.x;
    const int chunk = (N_NODES + 1023) / 1024;   // 98
    const int lo = t * chunk;
    const int hi = (lo + chunk < N_NODES) ? lo + chunk : N_NODES;

    int s = 0;
    for (int i = lo; i < hi; i++) s += g_deg[i];
    sm[t] = s;
    __syncthreads();

    // inclusive Hillis-Steele scan
    #pragma unroll
    for (int d = 1; d < 1024; d <<= 1) {
        int v = (t >= d) ? sm[t - d] : 0;
        __syncthreads();
        sm[t] += v;
        __syncthreads();
    }
    int run = sm[t] - s;  // exclusive prefix for this chunk

    for (int i = lo; i < hi; i++) {
        const int d = g_deg[i];
        g_off[i] = run;
        g_cursor[i] = run;
        run += d;
    }
    if (t == 1023) g_off[N_NODES] = run;
}

// ---------------- K4: exp + CSR scatter -------------------------------------
__global__ void k_edge2(const void* __restrict__ ei) {
    const int e = blockIdx.x * blockDim.x + threadIdx.x;
    if (e >= E_EDGES) return;
    int src, dst;
    load_edge(ei, e, src, dst);
    const float4 al = *(const float4*)(g_alpha + (size_t)e * 4);
    const uint4 m = *(const uint4*)(g_segmax + (size_t)dst * 4);
    float4 ex;
    ex.x = __expf(al.x - fdec(m.x));
    ex.y = __expf(al.y - fdec(m.y));
    ex.z = __expf(al.z - fdec(m.z));
    ex.w = __expf(al.w - fdec(m.w));
    const int pos = atomicAdd(&g_cursor[dst], 1);
    g_csr_src[pos] = src;
    *(float4*)(g_csr_w + (size_t)pos * 4) = ex;
}

// ---------------- K5: per-node aggregation (1 warp / node, no atomics) -----
__global__ void __launch_bounds__(256) k_aggregate(float* __restrict__ out,
                                                   const float* __restrict__ bias) {
    const int n = (blockIdx.x * blockDim.x + threadIdx.x) >> 5;
    if (n >= N_NODES) return;
    const int lane = threadIdx.x & 31;
    const int head = lane >> 3;

    const int beg = __ldg(g_off + n);
    const int end = __ldg(g_off + n + 1);

    float4 acc = make_float4(0.f, 0.f, 0.f, 0.f);
    float sumw = 0.f;

    for (int p = beg; p < end; p++) {
        const int src = __ldg(g_csr_src + p);                       // warp broadcast
        const float w = __ldg(g_csr_w + (size_t)p * 4 + head);
        const float4 hv = *(const float4*)(g_h + (size_t)src * OC + lane * 4);
        acc.x = fmaf(w, hv.x, acc.x);
        acc.y = fmaf(w, hv.y, acc.y);
        acc.z = fmaf(w, hv.z, acc.z);
        acc.w = fmaf(w, hv.w, acc.w);
        sumw += w;
    }

    const float r = 1.f / (sumw + 1e-16f);
    const float4 b4 = __ldg((const float4*)(bias + lane * 4));
    float4 o;
    o.x = fmaf(acc.x, r, b4.x);
    o.y = fmaf(acc.y, r, b4.y);
    o.z = fmaf(acc.z, r, b4.z);
    o.w = fmaf(acc.w, r, b4.w);
    *(float4*)(out + (size_t)n * OC + lane * 4) = o;
}

// ---------------- launch ----------------
extern "C" void kernel_launch(void* const* d_in, const int* in_sizes, int n_in,
                              void* d_out, int out_size) {
    const float* x    = (const float*)d_in[0];
    const void*  ei   = d_in[1];
    const float* W    = (const float*)d_in[2];
    const float* att  = (const float*)d_in[3];
    const float* bias = (const float*)d_in[4];
    float*       out  = (float*)d_out;

    (void)in_sizes; (void)n_in; (void)out_size;

    k_detect<<<1, 32>>>((const unsigned*)ei);
    k_init_deg<<<(N_NODES + 255) / 256, 256>>>();
    k_gemm<<<N_NODES / 32, 128>>>(x, W, att);
    k_edge1<<<(E_EDGES + 255) / 256, 256>>>(ei);
    k_scan<<<1, 1024>>>();
    k_edge2<<<(E_EDGES + 255) / 256, 256>>>(ei);
    k_aggregate<<<(N_NODES * 32 + 255) / 256, 256>>>(out, bias);
}

// round 5
// speedup vs baseline: 1.3334x; 1.1821x over previous
#include <cuda_runtime.h>
#include <cuda_fp16.h>
#include <cstdint>

#define N_NODES 100000
#define E_EDGES 1600000
#define IN_CH   128
#define HEADS   4
#define OUT_CH  32
#define OC      (HEADS * OUT_CH)   // 128
#define NEG_SLOPE 0.2f

// ---------------- scratch (device globals; no allocation allowed) ----------
__device__ __align__(16) __half g_hh[(size_t)N_NODES * OC];          // 25.6 MB (fp16 h)
__device__ __align__(16) float  g_ssrc[N_NODES * HEADS];
__device__ __align__(16) float  g_sdst[N_NODES * HEADS];
__device__ __align__(16) float  g_csr_w[(size_t)E_EDGES * HEADS];    // 25.6 MB
__device__ int g_csr_src[E_EDGES];                                   // 6.4 MB
__device__ int g_deg[N_NODES];
__device__ int g_off[N_NODES + 1];
__device__ int g_cursor[N_NODES];
__device__ unsigned g_maxss[HEADS];   // order-encoded global max of ss per head
__device__ int g_is64;

// order-preserving float<->uint encode for atomicMax on signed floats
__device__ __forceinline__ unsigned fenc(float f) {
    unsigned u = __float_as_uint(f);
    return (u & 0x80000000u) ? ~u : (u | 0x80000000u);
}
__device__ __forceinline__ float fdec(unsigned u) {
    return (u & 0x80000000u) ? __uint_as_float(u ^ 0x80000000u)
                             : __uint_as_float(~u);
}
__device__ __forceinline__ float leaky(float v) {
    return (v >= 0.f) ? v : NEG_SLOPE * v;
}

// ---------------- K0: detect edge_index dtype -------------------------------
__global__ void k_detect(const unsigned* __restrict__ ei32) {
    if (threadIdx.x == 0 && blockIdx.x == 0) {
        int allzero = 1;
        #pragma unroll 1
        for (int i = 0; i < 64; i++)
            if (ei32[2 * i + 1] != 0u) { allzero = 0; break; }
        g_is64 = allzero;
    }
}

__global__ void k_init() {
    const int i = blockIdx.x * blockDim.x + threadIdx.x;
    if (i < N_NODES) g_deg[i] = 0;
    if (i < HEADS) g_maxss[i] = fenc(-__int_as_float(0x7f800000));
}

// ---------------- K1: h = x @ W (+fused scores, per-head global max) -------
// block = 128 threads (4 warps), 32 nodes per block.
__global__ void __launch_bounds__(128) k_gemm(const float* __restrict__ x,
                                              const float* __restrict__ W,
                                              const float* __restrict__ att) {
    __shared__ float xs[32][IN_CH];                    // 16 KB
    const int nbase = blockIdx.x * 32;
    const int t = threadIdx.x;

    #pragma unroll
    for (int i = t; i < 32 * IN_CH; i += 128) {
        int node = i >> 7, k = i & 127;
        xs[node][k] = x[(size_t)(nbase + node) * IN_CH + k];
    }
    __syncthreads();

    const int lane = t & 31;
    const int c0 = lane * 4;
    const int j0 = (t >> 5) * 8;
    const int head = lane >> 3;

    float4 acc[8];
    #pragma unroll
    for (int j = 0; j < 8; j++) acc[j] = make_float4(0.f, 0.f, 0.f, 0.f);

    #pragma unroll 4
    for (int k = 0; k < IN_CH; k++) {
        const float4 w4 = __ldg((const float4*)(W + (size_t)k * OC + c0));
        #pragma unroll
        for (int j = 0; j < 8; j++) {
            const float xv = xs[j0 + j][k];
            acc[j].x = fmaf(xv, w4.x, acc[j].x);
            acc[j].y = fmaf(xv, w4.y, acc[j].y);
            acc[j].z = fmaf(xv, w4.z, acc[j].z);
            acc[j].w = fmaf(xv, w4.w, acc[j].w);
        }
    }

    // store h in fp16 (consumed only by the aggregate gather)
    #pragma unroll
    for (int j = 0; j < 8; j++) {
        __half h4[4] = {__float2half_rn(acc[j].x), __float2half_rn(acc[j].y),
                        __float2half_rn(acc[j].z), __float2half_rn(acc[j].w)};
        *(uint2*)(g_hh + (size_t)(nbase + j0 + j) * OC + c0) = *(uint2*)h4;
    }

    // ---- fused attention scores ----
    const int kloc = c0 & 31;
    const float4 as4 = __ldg((const float4*)(att + head * 2 * OUT_CH + kloc));
    const float4 ad4 = __ldg((const float4*)(att + head * 2 * OUT_CH + OUT_CH + kloc));

    float mymax = -__int_as_float(0x7f800000);
    #pragma unroll
    for (int j = 0; j < 8; j++) {
        float ss = acc[j].x * as4.x + acc[j].y * as4.y + acc[j].z * as4.z + acc[j].w * as4.w;
        float sd = acc[j].x * ad4.x + acc[j].y * ad4.y + acc[j].z * ad4.z + acc[j].w * ad4.w;
        #pragma unroll
        for (int off = 4; off; off >>= 1) {
            ss += __shfl_xor_sync(0xffffffffu, ss, off);
            sd += __shfl_xor_sync(0xffffffffu, sd, off);
        }
        mymax = fmaxf(mymax, ss);               // all 8 lanes hold full ss
        if ((lane & 7) == j) {
            const int idx = (nbase + j0 + j) * 4 + head;
            g_ssrc[idx] = ss;
            g_sdst[idx] = sd;
        }
    }
    if ((lane & 7) == 0)
        atomicMax(&g_maxss[head], fenc(mymax));
}

// ---------------- K2: degree histogram (reads dst only) --------------------
__global__ void k_hist(const void* __restrict__ ei) {
    const int e = blockIdx.x * blockDim.x + threadIdx.x;
    if (e >= E_EDGES) return;
    int dst;
    if (g_is64) dst = (int)((const long long*)ei)[E_EDGES + e];
    else        dst = ((const int*)ei)[E_EDGES + e];
    atomicAdd(&g_deg[dst], 1);
}

// ---------------- K3: exclusive prefix scan of degrees (1 block) -----------
__global__ void __launch_bounds__(1024) k_scan() {
    __shared__ int sm[1024];
    const int t = threadIdx.x;
    const int chunk = (N_NODES + 1023) / 1024;   // 98
    const int lo = t * chunk;
    const int hi = (lo + chunk < N_NODES) ? lo + chunk : N_NODES;

    int s = 0;
    for (int i = lo; i < hi; i++) s += g_deg[i];
    sm[t] = s;
    __syncthreads();

    #pragma unroll
    for (int d = 1; d < 1024; d <<= 1) {
        int v = (t >= d) ? sm[t - d] : 0;
        __syncthreads();
        sm[t] += v;
        __syncthreads();
    }
    int run = sm[t] - s;

    for (int i = lo; i < hi; i++) {
        const int d = g_deg[i];
        g_off[i] = run;
        g_cursor[i] = run;
        run += d;
    }
    if (t == 1023) g_off[N_NODES] = run;
}

// ---------------- K4: alpha + exp(bounded) + CSR scatter --------------------
__global__ void k_edge2(const void* __restrict__ ei) {
    const int e = blockIdx.x * blockDim.x + threadIdx.x;
    if (e >= E_EDGES) return;
    int src, dst;
    if (g_is64) {
        const long long* p = (const long long*)ei;
        src = (int)p[e]; dst = (int)p[E_EDGES + e];
    } else {
        const int* p = (const int*)ei;
        src = p[e]; dst = p[E_EDGES + e];
    }
    const float4 a = *(const float4*)(g_ssrc + (size_t)src * 4);
    const float4 b = *(const float4*)(g_sdst + (size_t)dst * 4);
    // per-head global-max bound (L2/L1-cached broadcast)
    const float m0 = fdec(g_maxss[0]), m1 = fdec(g_maxss[1]);
    const float m2 = fdec(g_maxss[2]), m3 = fdec(g_maxss[3]);
    float4 ex;
    ex.x = __expf(leaky(a.x + b.x) - leaky(m0 + b.x));
    ex.y = __expf(leaky(a.y + b.y) - leaky(m1 + b.y));
    ex.z = __expf(leaky(a.z + b.z) - leaky(m2 + b.z));
    ex.w = __expf(leaky(a.w + b.w) - leaky(m3 + b.w));
    const int pos = atomicAdd(&g_cursor[dst], 1);
    g_csr_src[pos] = src;
    *(float4*)(g_csr_w + (size_t)pos * 4) = ex;
}

// ---------------- K5: per-node aggregation (1 warp / node, no atomics) -----
__global__ void __launch_bounds__(256) k_aggregate(float* __restrict__ out,
                                                   const float* __restrict__ bias) {
    const int n = (blockIdx.x * blockDim.x + threadIdx.x) >> 5;
    if (n >= N_NODES) return;
    const int lane = threadIdx.x & 31;
    const int head = lane >> 3;
    const int c0 = lane * 4;

    const int beg = __ldg(g_off + n);
    const int end = __ldg(g_off + n + 1);

    float4 acc = make_float4(0.f, 0.f, 0.f, 0.f);
    float sumw = 0.f;

    int p = beg;
    for (; p + 2 <= end; p += 2) {
        const int s0 = __ldg(g_csr_src + p);
        const int s1 = __ldg(g_csr_src + p + 1);
        const float w0 = __ldg(g_csr_w + (size_t)p * 4 + head);
        const float w1 = __ldg(g_csr_w + (size_t)(p + 1) * 4 + head);
        const uint2 r0 = *(const uint2*)(g_hh + (size_t)s0 * OC + c0);
        const uint2 r1 = *(const uint2*)(g_hh + (size_t)s1 * OC + c0);
        const float2 a0 = __half22float2(*(const __half2*)&r0.x);
        const float2 b0 = __half22float2(*(const __half2*)&r0.y);
        const float2 a1 = __half22float2(*(const __half2*)&r1.x);
        const float2 b1 = __half22float2(*(const __half2*)&r1.y);
        acc.x = fmaf(w0, a0.x, acc.x); acc.y = fmaf(w0, a0.y, acc.y);
        acc.z = fmaf(w0, b0.x, acc.z); acc.w = fmaf(w0, b0.y, acc.w);
        acc.x = fmaf(w1, a1.x, acc.x); acc.y = fmaf(w1, a1.y, acc.y);
        acc.z = fmaf(w1, b1.x, acc.z); acc.w = fmaf(w1, b1.y, acc.w);
        sumw += w0 + w1;
    }
    if (p < end) {
        const int s0 = __ldg(g_csr_src + p);
        const float w0 = __ldg(g_csr_w + (size_t)p * 4 + head);
        const uint2 r0 = *(const uint2*)(g_hh + (size_t)s0 * OC + c0);
        const float2 a0 = __half22float2(*(const __half2*)&r0.x);
        const float2 b0 = __half22float2(*(const __half2*)&r0.y);
        acc.x = fmaf(w0, a0.x, acc.x); acc.y = fmaf(w0, a0.y, acc.y);
        acc.z = fmaf(w0, b0.x, acc.z); acc.w = fmaf(w0, b0.y, acc.w);
        sumw += w0;
    }

    const float r = 1.f / (sumw + 1e-16f);
    const float4 b4 = __ldg((const float4*)(bias + c0));
    float4 o;
    o.x = fmaf(acc.x, r, b4.x);
    o.y = fmaf(acc.y, r, b4.y);
    o.z = fmaf(acc.z, r, b4.z);
    o.w = fmaf(acc.w, r, b4.w);
    *(float4*)(out + (size_t)n * OC + c0) = o;
}

// ---------------- launch ----------------
extern "C" void kernel_launch(void* const* d_in, const int* in_sizes, int n_in,
                              void* d_out, int out_size) {
    const float* x    = (const float*)d_in[0];
    const void*  ei   = d_in[1];
    const float* W    = (const float*)d_in[2];
    const float* att  = (const float*)d_in[3];
    const float* bias = (const float*)d_in[4];
    float*       out  = (float*)d_out;

    (void)in_sizes; (void)n_in; (void)out_size;

    k_detect<<<1, 32>>>((const unsigned*)ei);
    k_init<<<(N_NODES + 255) / 256, 256>>>();
    k_gemm<<<N_NODES / 32, 128>>>(x, W, att);
    k_hist<<<(E_EDGES + 255) / 256, 256>>>(ei);
    k_scan<<<1, 1024>>>();
    k_edge2<<<(E_EDGES + 255) / 256, 256>>>(ei);
    k_aggregate<<<(N_NODES * 32 + 255) / 256, 256>>>(out, bias);
}

// round 6
// speedup vs baseline: 1.3586x; 1.0189x over previous
#include <cuda_runtime.h>
#include <cuda_fp16.h>
#include <cstdint>

#define N_NODES 100000
#define E_EDGES 1600000
#define IN_CH   128
#define HEADS   4
#define OUT_CH  32
#define OC      (HEADS * OUT_CH)   // 128
#define NEG_SLOPE 0.2f

// ---------------- scratch (device globals; no allocation allowed) ----------
__device__ __align__(16) __half g_hh[(size_t)N_NODES * OC];   // 25.6 MB (fp16 h)
__device__ __align__(16) float  g_ssrc[N_NODES * HEADS];
__device__ __align__(16) float  g_sdst[N_NODES * HEADS];
__device__ __align__(16) uint4  g_csr[E_EDGES];               // 25.6 MB {src, w01, w23, pad}
__device__ int g_deg[N_NODES];
__device__ int g_off[N_NODES + 1];
__device__ int g_cursor[N_NODES];
__device__ unsigned g_maxss[HEADS];   // order-encoded global max of ss per head
__device__ int g_is64;

// order-preserving float<->uint encode for atomicMax on signed floats
__device__ __forceinline__ unsigned fenc(float f) {
    unsigned u = __float_as_uint(f);
    return (u & 0x80000000u) ? ~u : (u | 0x80000000u);
}
__device__ __forceinline__ float fdec(unsigned u) {
    return (u & 0x80000000u) ? __uint_as_float(u ^ 0x80000000u)
                             : __uint_as_float(~u);
}
__device__ __forceinline__ float leaky(float v) {
    return (v >= 0.f) ? v : NEG_SLOPE * v;
}

// ---------------- K0: detect edge_index dtype -------------------------------
__global__ void k_detect(const unsigned* __restrict__ ei32) {
    if (threadIdx.x == 0 && blockIdx.x == 0) {
        int allzero = 1;
        #pragma unroll 1
        for (int i = 0; i < 64; i++)
            if (ei32[2 * i + 1] != 0u) { allzero = 0; break; }
        g_is64 = allzero;
    }
}

__global__ void k_init() {
    const int i = blockIdx.x * blockDim.x + threadIdx.x;
    if (i < N_NODES) g_deg[i] = 0;
    if (i < HEADS) g_maxss[i] = fenc(-__int_as_float(0x7f800000));
}

// ---------------- K1: h = x @ W (+fused scores, per-head global max) -------
__global__ void __launch_bounds__(128) k_gemm(const float* __restrict__ x,
                                              const float* __restrict__ W,
                                              const float* __restrict__ att) {
    __shared__ float xs[32][IN_CH];                    // 16 KB
    const int nbase = blockIdx.x * 32;
    const int t = threadIdx.x;

    #pragma unroll
    for (int i = t; i < 32 * IN_CH; i += 128) {
        int node = i >> 7, k = i & 127;
        xs[node][k] = x[(size_t)(nbase + node) * IN_CH + k];
    }
    __syncthreads();

    const int lane = t & 31;
    const int c0 = lane * 4;
    const int j0 = (t >> 5) * 8;
    const int head = lane >> 3;

    float4 acc[8];
    #pragma unroll
    for (int j = 0; j < 8; j++) acc[j] = make_float4(0.f, 0.f, 0.f, 0.f);

    #pragma unroll 4
    for (int k = 0; k < IN_CH; k++) {
        const float4 w4 = __ldg((const float4*)(W + (size_t)k * OC + c0));
        #pragma unroll
        for (int j = 0; j < 8; j++) {
            const float xv = xs[j0 + j][k];
            acc[j].x = fmaf(xv, w4.x, acc[j].x);
            acc[j].y = fmaf(xv, w4.y, acc[j].y);
            acc[j].z = fmaf(xv, w4.z, acc[j].z);
            acc[j].w = fmaf(xv, w4.w, acc[j].w);
        }
    }

    // store h in fp16 (consumed only by the aggregate gather)
    #pragma unroll
    for (int j = 0; j < 8; j++) {
        __half h4[4] = {__float2half_rn(acc[j].x), __float2half_rn(acc[j].y),
                        __float2half_rn(acc[j].z), __float2half_rn(acc[j].w)};
        *(uint2*)(g_hh + (size_t)(nbase + j0 + j) * OC + c0) = *(uint2*)h4;
    }

    // ---- fused attention scores ----
    const int kloc = c0 & 31;
    const float4 as4 = __ldg((const float4*)(att + head * 2 * OUT_CH + kloc));
    const float4 ad4 = __ldg((const float4*)(att + head * 2 * OUT_CH + OUT_CH + kloc));

    float mymax = -__int_as_float(0x7f800000);
    #pragma unroll
    for (int j = 0; j < 8; j++) {
        float ss = acc[j].x * as4.x + acc[j].y * as4.y + acc[j].z * as4.z + acc[j].w * as4.w;
        float sd = acc[j].x * ad4.x + acc[j].y * ad4.y + acc[j].z * ad4.z + acc[j].w * ad4.w;
        #pragma unroll
        for (int off = 4; off; off >>= 1) {
            ss += __shfl_xor_sync(0xffffffffu, ss, off);
            sd += __shfl_xor_sync(0xffffffffu, sd, off);
        }
        mymax = fmaxf(mymax, ss);
        if ((lane & 7) == j) {
            const int idx = (nbase + j0 + j) * 4 + head;
            g_ssrc[idx] = ss;
            g_sdst[idx] = sd;
        }
    }
    if ((lane & 7) == 0)
        atomicMax(&g_maxss[head], fenc(mymax));
}

// ---------------- K2: degree histogram (reads dst only) --------------------
__global__ void k_hist(const void* __restrict__ ei) {
    const int e = blockIdx.x * blockDim.x + threadIdx.x;
    if (e >= E_EDGES) return;
    int dst;
    if (g_is64) dst = (int)((const long long*)ei)[E_EDGES + e];
    else        dst = ((const int*)ei)[E_EDGES + e];
    atomicAdd(&g_deg[dst], 1);
}

// ---------------- K3: exclusive prefix scan of degrees (1 block) -----------
__global__ void __launch_bounds__(1024) k_scan() {
    __shared__ int sm[1024];
    const int t = threadIdx.x;
    const int chunk = (N_NODES + 1023) / 1024;   // 98
    const int lo = t * chunk;
    const int hi = (lo + chunk < N_NODES) ? lo + chunk : N_NODES;

    int s = 0;
    for (int i = lo; i < hi; i++) s += g_deg[i];
    sm[t] = s;
    __syncthreads();

    #pragma unroll
    for (int d = 1; d < 1024; d <<= 1) {
        int v = (t >= d) ? sm[t - d] : 0;
        __syncthreads();
        sm[t] += v;
        __syncthreads();
    }
    int run = sm[t] - s;

    for (int i = lo; i < hi; i++) {
        const int d = g_deg[i];
        g_off[i] = run;
        g_cursor[i] = run;
        run += d;
    }
    if (t == 1023) g_off[N_NODES] = run;
}

// ---------------- K4: alpha + exp(bounded) + fused CSR record scatter ------
__global__ void k_edge2(const void* __restrict__ ei) {
    const int e = blockIdx.x * blockDim.x + threadIdx.x;
    if (e >= E_EDGES) return;
    int src, dst;
    if (g_is64) {
        const long long* p = (const long long*)ei;
        src = (int)p[e]; dst = (int)p[E_EDGES + e];
    } else {
        const int* p = (const int*)ei;
        src = p[e]; dst = p[E_EDGES + e];
    }
    const float4 a = *(const float4*)(g_ssrc + (size_t)src * 4);
    const float4 b = *(const float4*)(g_sdst + (size_t)dst * 4);
    const float m0 = fdec(g_maxss[0]), m1 = fdec(g_maxss[1]);
    const float m2 = fdec(g_maxss[2]), m3 = fdec(g_maxss[3]);
    const float ex0 = __expf(leaky(a.x + b.x) - leaky(m0 + b.x));
    const float ex1 = __expf(leaky(a.y + b.y) - leaky(m1 + b.y));
    const float ex2 = __expf(leaky(a.z + b.z) - leaky(m2 + b.z));
    const float ex3 = __expf(leaky(a.w + b.w) - leaky(m3 + b.w));

    const __half2 w01 = __floats2half2_rn(ex0, ex1);
    const __half2 w23 = __floats2half2_rn(ex2, ex3);

    uint4 rec;
    rec.x = (unsigned)src;
    rec.y = *(const unsigned*)&w01;
    rec.z = *(const unsigned*)&w23;
    rec.w = 0;

    const int pos = atomicAdd(&g_cursor[dst], 1);
    g_csr[pos] = rec;
}

// ---------------- K5: per-node aggregation (1 warp / node, no atomics) -----
__device__ __forceinline__ float rec_weight(const uint4& rec, int head) {
    const unsigned pair = (head < 2) ? rec.y : rec.z;
    const __half2 h2 = *(const __half2*)&pair;
    return (head & 1) ? __high2float(h2) : __low2float(h2);
}

__device__ __forceinline__ void rec_fma(const uint4& rec, int head, int c0,
                                        float4& acc, float& sumw) {
    const float w = rec_weight(rec, head);
    const uint2 r = *(const uint2*)(g_hh + (size_t)rec.x * OC + c0);
    const float2 a = __half22float2(*(const __half2*)&r.x);
    const float2 b = __half22float2(*(const __half2*)&r.y);
    acc.x = fmaf(w, a.x, acc.x); acc.y = fmaf(w, a.y, acc.y);
    acc.z = fmaf(w, b.x, acc.z); acc.w = fmaf(w, b.y, acc.w);
    sumw += w;
}

__global__ void __launch_bounds__(256) k_aggregate(float* __restrict__ out,
                                                   const float* __restrict__ bias) {
    const int n = (blockIdx.x * blockDim.x + threadIdx.x) >> 5;
    if (n >= N_NODES) return;
    const int lane = threadIdx.x & 31;
    const int head = lane >> 3;
    const int c0 = lane * 4;

    const int beg = __ldg(g_off + n);
    const int end = __ldg(g_off + n + 1);

    float4 acc = make_float4(0.f, 0.f, 0.f, 0.f);
    float sumw = 0.f;

    int p = beg;
    for (; p + 4 <= end; p += 4) {
        const uint4 r0 = g_csr[p];
        const uint4 r1 = g_csr[p + 1];
        const uint4 r2 = g_csr[p + 2];
        const uint4 r3 = g_csr[p + 3];
        rec_fma(r0, head, c0, acc, sumw);
        rec_fma(r1, head, c0, acc, sumw);
        rec_fma(r2, head, c0, acc, sumw);
        rec_fma(r3, head, c0, acc, sumw);
    }
    for (; p < end; p++) {
        const uint4 r0 = g_csr[p];
        rec_fma(r0, head, c0, acc, sumw);
    }

    const float r = 1.f / (sumw + 1e-16f);
    const float4 b4 = __ldg((const float4*)(bias + c0));
    float4 o;
    o.x = fmaf(acc.x, r, b4.x);
    o.y = fmaf(acc.y, r, b4.y);
    o.z = fmaf(acc.z, r, b4.z);
    o.w = fmaf(acc.w, r, b4.w);
    *(float4*)(out + (size_t)n * OC + c0) = o;
}

// ---------------- launch ----------------
extern "C" void kernel_launch(void* const* d_in, const int* in_sizes, int n_in,
                              void* d_out, int out_size) {
    const float* x    = (const float*)d_in[0];
    const void*  ei   = d_in[1];
    const float* W    = (const float*)d_in[2];
    const float* att  = (const float*)d_in[3];
    const float* bias = (const float*)d_in[4];
    float*       out  = (float*)d_out;

    (void)in_sizes; (void)n_in; (void)out_size;

    k_detect<<<1, 32>>>((const unsigned*)ei);
    k_init<<<(N_NODES + 255) / 256, 256>>>();
    k_gemm<<<N_NODES / 32, 128>>>(x, W, att);
    k_hist<<<(E_EDGES + 255) / 256, 256>>>(ei);
    k_scan<<<1, 1024>>>();
    k_edge2<<<(E_EDGES + 255) / 256, 256>>>(ei);
    k_aggregate<<<(N_NODES * 32 + 255) / 256, 256>>>(out, bias);
}

// round 7
// speedup vs baseline: 1.3823x; 1.0174x over previous
#include <cuda_runtime.h>
#include <cuda_fp16.h>
#include <cstdint>

#define N_NODES 100000
#define E_EDGES 1600000
#define IN_CH   128
#define HEADS   4
#define OUT_CH  32
#define OC      (HEADS * OUT_CH)   // 128
#define NEG_SLOPE 0.2f

// ---------------- scratch (device globals; no allocation allowed) ----------
__device__ __align__(16) __half g_hh[(size_t)N_NODES * OC];   // 25.6 MB (fp16 h)
__device__ __align__(16) float  g_ssrc[N_NODES * HEADS];      // 1.6 MB
__device__ __align__(16) float  g_sdst[N_NODES * HEADS];      // 1.6 MB
__device__ int g_csr_src[E_EDGES];                            // 6.4 MB
__device__ int g_deg[N_NODES];
__device__ int g_off[N_NODES + 1];
__device__ int g_cursor[N_NODES];
__device__ unsigned g_maxss[HEADS];   // order-encoded global max of ss per head
__device__ int g_is64;

// order-preserving float<->uint encode for atomicMax on signed floats
__device__ __forceinline__ unsigned fenc(float f) {
    unsigned u = __float_as_uint(f);
    return (u & 0x80000000u) ? ~u : (u | 0x80000000u);
}
__device__ __forceinline__ float fdec(unsigned u) {
    return (u & 0x80000000u) ? __uint_as_float(u ^ 0x80000000u)
                             : __uint_as_float(~u);
}
__device__ __forceinline__ float leaky(float v) {
    return (v >= 0.f) ? v : NEG_SLOPE * v;
}

// ---------------- K0: init + dtype detect -----------------------------------
__global__ void k_init(const unsigned* __restrict__ ei32) {
    const int i = blockIdx.x * blockDim.x + threadIdx.x;
    if (i < N_NODES) g_deg[i] = 0;
    if (i < HEADS) g_maxss[i] = fenc(-__int_as_float(0x7f800000));
    if (i == 0) {
        int allzero = 1;
        #pragma unroll 1
        for (int k = 0; k < 64; k++)
            if (ei32[2 * k + 1] != 0u) { allzero = 0; break; }
        g_is64 = allzero;
    }
}

// ---------------- K1: h = x @ W (+fused scores, per-head global max) -------
__global__ void __launch_bounds__(128) k_gemm(const float* __restrict__ x,
                                              const float* __restrict__ W,
                                              const float* __restrict__ att) {
    __shared__ float xs[32][IN_CH];                    // 16 KB
    const int nbase = blockIdx.x * 32;
    const int t = threadIdx.x;

    #pragma unroll
    for (int i = t; i < 32 * IN_CH; i += 128) {
        int node = i >> 7, k = i & 127;
        xs[node][k] = x[(size_t)(nbase + node) * IN_CH + k];
    }
    __syncthreads();

    const int lane = t & 31;
    const int c0 = lane * 4;
    const int j0 = (t >> 5) * 8;
    const int head = lane >> 3;

    float4 acc[8];
    #pragma unroll
    for (int j = 0; j < 8; j++) acc[j] = make_float4(0.f, 0.f, 0.f, 0.f);

    #pragma unroll 4
    for (int k = 0; k < IN_CH; k++) {
        const float4 w4 = __ldg((const float4*)(W + (size_t)k * OC + c0));
        #pragma unroll
        for (int j = 0; j < 8; j++) {
            const float xv = xs[j0 + j][k];
            acc[j].x = fmaf(xv, w4.x, acc[j].x);
            acc[j].y = fmaf(xv, w4.y, acc[j].y);
            acc[j].z = fmaf(xv, w4.z, acc[j].z);
            acc[j].w = fmaf(xv, w4.w, acc[j].w);
        }
    }

    // store h in fp16 (consumed only by the aggregate gather)
    #pragma unroll
    for (int j = 0; j < 8; j++) {
        __half h4[4] = {__float2half_rn(acc[j].x), __float2half_rn(acc[j].y),
                        __float2half_rn(acc[j].z), __float2half_rn(acc[j].w)};
        *(uint2*)(g_hh + (size_t)(nbase + j0 + j) * OC + c0) = *(uint2*)h4;
    }

    // ---- fused attention scores ----
    const int kloc = c0 & 31;
    const float4 as4 = __ldg((const float4*)(att + head * 2 * OUT_CH + kloc));
    const float4 ad4 = __ldg((const float4*)(att + head * 2 * OUT_CH + OUT_CH + kloc));

    float mymax = -__int_as_float(0x7f800000);
    #pragma unroll
    for (int j = 0; j < 8; j++) {
        float ss = acc[j].x * as4.x + acc[j].y * as4.y + acc[j].z * as4.z + acc[j].w * as4.w;
        float sd = acc[j].x * ad4.x + acc[j].y * ad4.y + acc[j].z * ad4.z + acc[j].w * ad4.w;
        #pragma unroll
        for (int off = 4; off; off >>= 1) {
            ss += __shfl_xor_sync(0xffffffffu, ss, off);
            sd += __shfl_xor_sync(0xffffffffu, sd, off);
        }
        mymax = fmaxf(mymax, ss);
        if ((lane & 7) == j) {
            const int idx = (nbase + j0 + j) * 4 + head;
            g_ssrc[idx] = ss;
            g_sdst[idx] = sd;
        }
    }
    if ((lane & 7) == 0)
        atomicMax(&g_maxss[head], fenc(mymax));
}

// ---------------- K2: degree histogram (reads dst only) --------------------
__global__ void k_hist(const void* __restrict__ ei) {
    const int e = blockIdx.x * blockDim.x + threadIdx.x;
    if (e >= E_EDGES) return;
    int dst;
    if (g_is64) dst = (int)((const long long*)ei)[E_EDGES + e];
    else        dst = ((const int*)ei)[E_EDGES + e];
    atomicAdd(&g_deg[dst], 1);
}

// ---------------- K3: exclusive prefix scan of degrees (1 block) -----------
__global__ void __launch_bounds__(1024) k_scan() {
    __shared__ int sm[1024];
    const int t = threadIdx.x;
    const int chunk = (N_NODES + 1023) / 1024;   // 98
    const int lo = t * chunk;
    const int hi = (lo + chunk < N_NODES) ? lo + chunk : N_NODES;

    int s = 0;
    for (int i = lo; i < hi; i++) s += g_deg[i];
    sm[t] = s;
    __syncthreads();

    #pragma unroll
    for (int d = 1; d < 1024; d <<= 1) {
        int v = (t >= d) ? sm[t - d] : 0;
        __syncthreads();
        sm[t] += v;
        __syncthreads();
    }
    int run = sm[t] - s;

    for (int i = lo; i < hi; i++) {
        const int d = g_deg[i];
        g_off[i] = run;
        g_cursor[i] = run;
        run += d;
    }
    if (t == 1023) g_off[N_NODES] = run;
}

// ---------------- K4: CSR position scatter (src only, 4 B) -----------------
__global__ void k_edge2(const void* __restrict__ ei) {
    const int e = blockIdx.x * blockDim.x + threadIdx.x;
    if (e >= E_EDGES) return;
    int src, dst;
    if (g_is64) {
        const long long* p = (const long long*)ei;
        src = (int)p[e]; dst = (int)p[E_EDGES + e];
    } else {
        const int* p = (const int*)ei;
        src = p[e]; dst = p[E_EDGES + e];
    }
    const int pos = atomicAdd(&g_cursor[dst], 1);
    g_csr_src[pos] = src;
}

// ---------------- K5: aggregation w/ on-the-fly softmax (1 warp/node) ------
__device__ __forceinline__ void edge_fma(int src, float sd, float bnd, int head, int c0,
                                         float4& acc, float& sumw) {
    const float ss = __ldg(g_ssrc + (size_t)src * 4 + head);
    const float w = __expf(leaky(ss + sd) - bnd);
    const uint2 r = *(const uint2*)(g_hh + (size_t)src * OC + c0);
    const float2 a = __half22float2(*(const __half2*)&r.x);
    const float2 b = __half22float2(*(const __half2*)&r.y);
    acc.x = fmaf(w, a.x, acc.x); acc.y = fmaf(w, a.y, acc.y);
    acc.z = fmaf(w, b.x, acc.z); acc.w = fmaf(w, b.y, acc.w);
    sumw += w;
}

__global__ void __launch_bounds__(256) k_aggregate(float* __restrict__ out,
                                                   const float* __restrict__ bias) {
    const int n = (blockIdx.x * blockDim.x + threadIdx.x) >> 5;
    if (n >= N_NODES) return;
    const int lane = threadIdx.x & 31;
    const int head = lane >> 3;
    const int c0 = lane * 4;

    const int beg = __ldg(g_off + n);
    const int end = __ldg(g_off + n + 1);

    const float sd = __ldg(g_sdst + (size_t)n * 4 + head);
    const float bnd = leaky(fdec(g_maxss[head]) + sd);   // per-head shift (softmax-invariant)

    float4 acc = make_float4(0.f, 0.f, 0.f, 0.f);
    float sumw = 0.f;

    int p = beg;
    for (; p + 4 <= end; p += 4) {
        const int s0 = __ldg(g_csr_src + p);
        const int s1 = __ldg(g_csr_src + p + 1);
        const int s2 = __ldg(g_csr_src + p + 2);
        const int s3 = __ldg(g_csr_src + p + 3);
        edge_fma(s0, sd, bnd, head, c0, acc, sumw);
        edge_fma(s1, sd, bnd, head, c0, acc, sumw);
        edge_fma(s2, sd, bnd, head, c0, acc, sumw);
        edge_fma(s3, sd, bnd, head, c0, acc, sumw);
    }
    for (; p < end; p++) {
        const int s0 = __ldg(g_csr_src + p);
        edge_fma(s0, sd, bnd, head, c0, acc, sumw);
    }

    const float r = 1.f / (sumw + 1e-16f);
    const float4 b4 = __ldg((const float4*)(bias + c0));
    float4 o;
    o.x = fmaf(acc.x, r, b4.x);
    o.y = fmaf(acc.y, r, b4.y);
    o.z = fmaf(acc.z, r, b4.z);
    o.w = fmaf(acc.w, r, b4.w);
    *(float4*)(out + (size_t)n * OC + c0) = o;
}

// ---------------- launch ----------------
extern "C" void kernel_launch(void* const* d_in, const int* in_sizes, int n_in,
                              void* d_out, int out_size) {
    const float* x    = (const float*)d_in[0];
    const void*  ei   = d_in[1];
    const float* W    = (const float*)d_in[2];
    const float* att  = (const float*)d_in[3];
    const float* bias = (const float*)d_in[4];
    float*       out  = (float*)d_out;

    (void)in_sizes; (void)n_in; (void)out_size;

    k_init<<<(N_NODES + 255) / 256, 256>>>((const unsigned*)ei);
    k_gemm<<<N_NODES / 32, 128>>>(x, W, att);
    k_hist<<<(E_EDGES + 255) / 256, 256>>>(ei);
    k_scan<<<1, 1024>>>();
    k_edge2<<<(E_EDGES + 255) / 256, 256>>>(ei);
    k_aggregate<<<(N_NODES * 32 + 255) / 256, 256>>>(out, bias);
}

// round 8
// speedup vs baseline: 2.4985x; 1.8076x over previous
#include <cuda_runtime.h>
#include <cuda_fp16.h>
#include <cstdint>

#define N_NODES 100000
#define E_EDGES 1600000
#define IN_CH   128
#define HEADS   4
#define OUT_CH  32
#define OC      (HEADS * OUT_CH)   // 128
#define NEG_SLOPE 0.2f

#define SCAN_BLK 1024
#define N_SCAN_BLOCKS ((N_NODES + SCAN_BLK - 1) / SCAN_BLK)   // 98

// ---------------- scratch (device globals; no allocation allowed) ----------
__device__ __align__(16) __half g_hh[(size_t)N_NODES * OC];   // 25.6 MB (fp16 h)
__device__ __align__(16) float  g_ssrc[N_NODES * HEADS];      // 1.6 MB
__device__ __align__(16) float  g_sdst[N_NODES * HEADS];      // 1.6 MB
__device__ int g_csr_src[E_EDGES];                            // 6.4 MB
__device__ int g_deg[N_NODES];
__device__ int g_off[N_NODES + 1];
__device__ int g_cursor[N_NODES];
__device__ int g_bsum[N_SCAN_BLOCKS];
__device__ int g_bpre[N_SCAN_BLOCKS];
__device__ unsigned g_maxss[HEADS];   // order-encoded global max of ss per head
__device__ int g_is64;

// order-preserving float<->uint encode for atomicMax on signed floats
__device__ __forceinline__ unsigned fenc(float f) {
    unsigned u = __float_as_uint(f);
    return (u & 0x80000000u) ? ~u : (u | 0x80000000u);
}
__device__ __forceinline__ float fdec(unsigned u) {
    return (u & 0x80000000u) ? __uint_as_float(u ^ 0x80000000u)
                             : __uint_as_float(~u);
}
__device__ __forceinline__ float leaky(float v) {
    return (v >= 0.f) ? v : NEG_SLOPE * v;
}

// ---------------- K0: init + dtype detect -----------------------------------
__global__ void k_init(const unsigned* __restrict__ ei32) {
    const int i = blockIdx.x * blockDim.x + threadIdx.x;
    if (i < N_NODES) g_deg[i] = 0;
    if (i < HEADS) g_maxss[i] = fenc(-__int_as_float(0x7f800000));
    if (i == 0) {
        int allzero = 1;
        #pragma unroll 1
        for (int k = 0; k < 64; k++)
            if (ei32[2 * k + 1] != 0u) { allzero = 0; break; }
        g_is64 = allzero;
    }
}

// ---------------- K1: h = x @ W (+fused scores, per-head global max) -------
__global__ void __launch_bounds__(128) k_gemm(const float* __restrict__ x,
                                              const float* __restrict__ W,
                                              const float* __restrict__ att) {
    __shared__ float xs[32][IN_CH];                    // 16 KB
    const int nbase = blockIdx.x * 32;
    const int t = threadIdx.x;

    #pragma unroll
    for (int i = t; i < 32 * IN_CH; i += 128) {
        int node = i >> 7, k = i & 127;
        xs[node][k] = x[(size_t)(nbase + node) * IN_CH + k];
    }
    __syncthreads();

    const int lane = t & 31;
    const int c0 = lane * 4;
    const int j0 = (t >> 5) * 8;
    const int head = lane >> 3;

    float4 acc[8];
    #pragma unroll
    for (int j = 0; j < 8; j++) acc[j] = make_float4(0.f, 0.f, 0.f, 0.f);

    #pragma unroll 4
    for (int k = 0; k < IN_CH; k++) {
        const float4 w4 = __ldg((const float4*)(W + (size_t)k * OC + c0));
        #pragma unroll
        for (int j = 0; j < 8; j++) {
            const float xv = xs[j0 + j][k];
            acc[j].x = fmaf(xv, w4.x, acc[j].x);
            acc[j].y = fmaf(xv, w4.y, acc[j].y);
            acc[j].z = fmaf(xv, w4.z, acc[j].z);
            acc[j].w = fmaf(xv, w4.w, acc[j].w);
        }
    }

    // store h in fp16 (consumed only by the aggregate gather)
    #pragma unroll
    for (int j = 0; j < 8; j++) {
        __half h4[4] = {__float2half_rn(acc[j].x), __float2half_rn(acc[j].y),
                        __float2half_rn(acc[j].z), __float2half_rn(acc[j].w)};
        *(uint2*)(g_hh + (size_t)(nbase + j0 + j) * OC + c0) = *(uint2*)h4;
    }

    // ---- fused attention scores ----
    const int kloc = c0 & 31;
    const float4 as4 = __ldg((const float4*)(att + head * 2 * OUT_CH + kloc));
    const float4 ad4 = __ldg((const float4*)(att + head * 2 * OUT_CH + OUT_CH + kloc));

    float mymax = -__int_as_float(0x7f800000);
    #pragma unroll
    for (int j = 0; j < 8; j++) {
        float ss = acc[j].x * as4.x + acc[j].y * as4.y + acc[j].z * as4.z + acc[j].w * as4.w;
        float sd = acc[j].x * ad4.x + acc[j].y * ad4.y + acc[j].z * ad4.z + acc[j].w * ad4.w;
        #pragma unroll
        for (int off = 4; off; off >>= 1) {
            ss += __shfl_xor_sync(0xffffffffu, ss, off);
            sd += __shfl_xor_sync(0xffffffffu, sd, off);
        }
        mymax = fmaxf(mymax, ss);
        if ((lane & 7) == j) {
            const int idx = (nbase + j0 + j) * 4 + head;
            g_ssrc[idx] = ss;
            g_sdst[idx] = sd;
        }
    }
    if ((lane & 7) == 0)
        atomicMax(&g_maxss[head], fenc(mymax));
}

// ---------------- K2: degree histogram (reads dst only) --------------------
__global__ void k_hist(const void* __restrict__ ei) {
    const int e = blockIdx.x * blockDim.x + threadIdx.x;
    if (e >= E_EDGES) return;
    int dst;
    if (g_is64) dst = (int)((const long long*)ei)[E_EDGES + e];
    else        dst = ((const int*)ei)[E_EDGES + e];
    atomicAdd(&g_deg[dst], 1);
}

// ---------------- K3a: per-block exclusive scan of deg ---------------------
__global__ void __launch_bounds__(SCAN_BLK) k_scan_local() {
    __shared__ int ws[32];
    const int t = threadIdx.x;
    const int lane = t & 31;
    const int warp = t >> 5;
    const int i = blockIdx.x * SCAN_BLK + t;

    const int val = (i < N_NODES) ? g_deg[i] : 0;

    // warp inclusive scan
    int v = val;
    #pragma unroll
    for (int d = 1; d < 32; d <<= 1) {
        const int u = __shfl_up_sync(0xffffffffu, v, d);
        if (lane >= d) v += u;
    }
    if (lane == 31) ws[warp] = v;
    __syncthreads();

    if (warp == 0) {
        int w = ws[lane];
        #pragma unroll
        for (int d = 1; d < 32; d <<= 1) {
            const int u = __shfl_up_sync(0xffffffffu, w, d);
            if (lane >= d) w += u;
        }
        ws[lane] = w;
    }
    __syncthreads();

    const int incl = v + (warp ? ws[warp - 1] : 0);
    if (i < N_NODES) g_off[i] = incl - val;           // local exclusive prefix
    if (t == SCAN_BLK - 1) g_bsum[blockIdx.x] = incl; // block total
}

// ---------------- K3b: scan block totals (1 block, 128 thr) ----------------
__global__ void __launch_bounds__(128) k_scan_bsum() {
    __shared__ int ws[4];
    const int t = threadIdx.x;
    const int lane = t & 31;
    const int warp = t >> 5;
    const int val = (t < N_SCAN_BLOCKS) ? g_bsum[t] : 0;

    int v = val;
    #pragma unroll
    for (int d = 1; d < 32; d <<= 1) {
        const int u = __shfl_up_sync(0xffffffffu, v, d);
        if (lane >= d) v += u;
    }
    if (lane == 31) ws[warp] = v;
    __syncthreads();
    int wpre = 0;
    #pragma unroll
    for (int w = 0; w < 4; w++) if (w < warp) wpre += ws[w];
    if (t < N_SCAN_BLOCKS) g_bpre[t] = v - val + wpre;
}

// ---------------- K3c: add block prefix, emit off/cursor --------------------
__global__ void __launch_bounds__(SCAN_BLK) k_scan_final() {
    const int i = blockIdx.x * SCAN_BLK + threadIdx.x;
    if (i < N_NODES) {
        const int o = g_off[i] + g_bpre[blockIdx.x];
        g_off[i] = o;
        g_cursor[i] = o;
    }
    if (i == 0) g_off[N_NODES] = E_EDGES;   // histogram totals all edges
}

// ---------------- K4: CSR position scatter (src only, 4 B) -----------------
__global__ void k_edge2(const void* __restrict__ ei) {
    const int e = blockIdx.x * blockDim.x + threadIdx.x;
    if (e >= E_EDGES) return;
    int src, dst;
    if (g_is64) {
        const long long* p = (const long long*)ei;
        src = (int)p[e]; dst = (int)p[E_EDGES + e];
    } else {
        const int* p = (const int*)ei;
        src = p[e]; dst = p[E_EDGES + e];
    }
    const int pos = atomicAdd(&g_cursor[dst], 1);
    g_csr_src[pos] = src;
}

// ---------------- K5: aggregation w/ on-the-fly softmax (1 warp/node) ------
__device__ __forceinline__ void edge_fma(int src, float sd, float bnd, int head, int c0,
                                         float4& acc, float& sumw) {
    const float ss = __ldg(g_ssrc + (size_t)src * 4 + head);
    const float w = __expf(leaky(ss + sd) - bnd);
    const uint2 r = *(const uint2*)(g_hh + (size_t)src * OC + c0);
    const float2 a = __half22float2(*(const __half2*)&r.x);
    const float2 b = __half22float2(*(const __half2*)&r.y);
    acc.x = fmaf(w, a.x, acc.x); acc.y = fmaf(w, a.y, acc.y);
    acc.z = fmaf(w, b.x, acc.z); acc.w = fmaf(w, b.y, acc.w);
    sumw += w;
}

__global__ void __launch_bounds__(256) k_aggregate(float* __restrict__ out,
                                                   const float* __restrict__ bias) {
    const int n = (blockIdx.x * blockDim.x + threadIdx.x) >> 5;
    if (n >= N_NODES) return;
    const int lane = threadIdx.x & 31;
    const int head = lane >> 3;
    const int c0 = lane * 4;

    const int beg = __ldg(g_off + n);
    const int end = __ldg(g_off + n + 1);

    const float sd = __ldg(g_sdst + (size_t)n * 4 + head);
    const float bnd = leaky(fdec(g_maxss[head]) + sd);   // per-head shift (softmax-invariant)

    float4 acc = make_float4(0.f, 0.f, 0.f, 0.f);
    float sumw = 0.f;

    int p = beg;
    for (; p + 4 <= end; p += 4) {
        const int s0 = __ldg(g_csr_src + p);
        const int s1 = __ldg(g_csr_src + p + 1);
        const int s2 = __ldg(g_csr_src + p + 2);
        const int s3 = __ldg(g_csr_src + p + 3);
        edge_fma(s0, sd, bnd, head, c0, acc, sumw);
        edge_fma(s1, sd, bnd, head, c0, acc, sumw);
        edge_fma(s2, sd, bnd, head, c0, acc, sumw);
        edge_fma(s3, sd, bnd, head, c0, acc, sumw);
    }
    for (; p < end; p++) {
        const int s0 = __ldg(g_csr_src + p);
        edge_fma(s0, sd, bnd, head, c0, acc, sumw);
    }

    const float r = 1.f / (sumw + 1e-16f);
    const float4 b4 = __ldg((const float4*)(bias + c0));
    float4 o;
    o.x = fmaf(acc.x, r, b4.x);
    o.y = fmaf(acc.y, r, b4.y);
    o.z = fmaf(acc.z, r, b4.z);
    o.w = fmaf(acc.w, r, b4.w);
    *(float4*)(out + (size_t)n * OC + c0) = o;
}

// ---------------- launch ----------------
extern "C" void kernel_launch(void* const* d_in, const int* in_sizes, int n_in,
                              void* d_out, int out_size) {
    const float* x    = (const float*)d_in[0];
    const void*  ei   = d_in[1];
    const float* W    = (const float*)d_in[2];
    const float* att  = (const float*)d_in[3];
    const float* bias = (const float*)d_in[4];
    float*       out  = (float*)d_out;

    (void)in_sizes; (void)n_in; (void)out_size;

    k_init<<<(N_NODES + 255) / 256, 256>>>((const unsigned*)ei);
    k_gemm<<<N_NODES / 32, 128>>>(x, W, att);
    k_hist<<<(E_EDGES + 255) / 256, 256>>>(ei);
    k_scan_local<<<N_SCAN_BLOCKS, SCAN_BLK>>>();
    k_scan_bsum<<<1, 128>>>();
    k_scan_final<<<N_SCAN_BLOCKS, SCAN_BLK>>>();
    k_edge2<<<(E_EDGES + 255) / 256, 256>>>(ei);
    k_aggregate<<<(N_NODES * 32 + 255) / 256, 256>>>(out, bias);
}

// round 9
// speedup vs baseline: 2.9012x; 1.1611x over previous
#include <cuda_runtime.h>
#include <cuda_fp16.h>
#include <cstdint>

#define N_NODES 100000
#define E_EDGES 1600000
#define IN_CH   128
#define HEADS   4
#define OUT_CH  32
#define OC      (HEADS * OUT_CH)   // 128
#define NEG_SLOPE 0.2f

#define SCAN_BLK 1024
#define N_SCAN_BLOCKS ((N_NODES + SCAN_BLK - 1) / SCAN_BLK)   // 98
#define GEMM_CTAS ((N_NODES + 127) / 128)                     // 782

// ---------------- scratch (device globals; no allocation allowed) ----------
__device__ __align__(16) __half g_hh[(size_t)GEMM_CTAS * 128 * OC]; // fp16 h (padded)
__device__ __align__(16) float  g_ssrc[N_NODES * HEADS];
__device__ __align__(16) float  g_sdst[N_NODES * HEADS];
__device__ int g_csr_src[E_EDGES];
__device__ int g_deg[N_NODES];
__device__ int g_off[N_NODES + 1];
__device__ int g_cursor[N_NODES];
__device__ int g_bsum[N_SCAN_BLOCKS];
__device__ int g_bpre[N_SCAN_BLOCKS];
__device__ unsigned g_maxss[HEADS];
__device__ int g_is64;

__device__ __forceinline__ unsigned fenc(float f) {
    unsigned u = __float_as_uint(f);
    return (u & 0x80000000u) ? ~u : (u | 0x80000000u);
}
__device__ __forceinline__ float fdec(unsigned u) {
    return (u & 0x80000000u) ? __uint_as_float(u ^ 0x80000000u)
                             : __uint_as_float(~u);
}
__device__ __forceinline__ float leaky(float v) {
    return (v >= 0.f) ? v : NEG_SLOPE * v;
}

__device__ __forceinline__ void mma16816(float& d0, float& d1, float& d2, float& d3,
                                         unsigned a0, unsigned a1, unsigned a2, unsigned a3,
                                         unsigned b0, unsigned b1) {
    asm volatile("mma.sync.aligned.m16n8k16.row.col.f32.f16.f16.f32 "
                 "{%0,%1,%2,%3}, {%4,%5,%6,%7}, {%8,%9}, {%0,%1,%2,%3};"
                 : "+f"(d0), "+f"(d1), "+f"(d2), "+f"(d3)
                 : "r"(a0), "r"(a1), "r"(a2), "r"(a3), "r"(b0), "r"(b1));
}

// ---------------- K0: init + dtype detect -----------------------------------
__global__ void k_init(const unsigned* __restrict__ ei32) {
    const int i = blockIdx.x * blockDim.x + threadIdx.x;
    if (i < N_NODES) g_deg[i] = 0;
    if (i < HEADS) g_maxss[i] = fenc(-__int_as_float(0x7f800000));
    if (i == 0) {
        int allzero = 1;
        #pragma unroll 1
        for (int k = 0; k < 64; k++)
            if (ei32[2 * k + 1] != 0u) { allzero = 0; break; }
        g_is64 = allzero;
    }
}

// ---------------- K1: tensor-core GEMM + fused scores -----------------------
// CTA: 256 thr (8 warps). M_TILE=128 (warp -> 16 rows), N=128, K in 2 phases of 64.
#define APAD 72   // 64 + 8 halves pad
__global__ void __launch_bounds__(256) k_gemm_mma(const float* __restrict__ x,
                                                  const float* __restrict__ W,
                                                  const float* __restrict__ att) {
    __shared__ __half As[128][APAD];
    __shared__ __half Bs[128][APAD];

    const int nbase = blockIdx.x * 128;
    const int t = threadIdx.x;
    const int wid = t >> 5;
    const int lane = t & 31;
    const int g = lane >> 2;      // group (row / n within tile)
    const int tid = lane & 3;     // thread-in-group

    float d[16][4];
    #pragma unroll
    for (int nt = 0; nt < 16; nt++)
        #pragma unroll
        for (int q = 0; q < 4; q++) d[nt][q] = 0.f;

    #pragma unroll
    for (int kp = 0; kp < 2; kp++) {
        // load A tile: rows nbase..+127, cols kp*64..+63, fp32 -> fp16
        #pragma unroll
        for (int i = 0; i < 8; i++) {
            const int id = t + i * 256;            // 0..2047
            const int row = id >> 4;
            const int c4 = (id & 15) * 4;
            const int node = nbase + row;
            float4 v = make_float4(0.f, 0.f, 0.f, 0.f);
            if (node < N_NODES)
                v = __ldg((const float4*)(x + (size_t)node * IN_CH + kp * 64 + c4));
            __half h4[4] = {__float2half_rn(v.x), __float2half_rn(v.y),
                            __float2half_rn(v.z), __float2half_rn(v.w)};
            *(uint2*)&As[row][c4] = *(uint2*)h4;
        }
        // load B tile (transposed W): Bs[n][k] = W[kp*64+k][n]
        #pragma unroll
        for (int i = 0; i < 8; i++) {
            const int id = t + i * 256;            // 0..2047
            const int k = id >> 5;
            const int n4 = (id & 31) * 4;
            const float4 w4 = __ldg((const float4*)(W + (size_t)(kp * 64 + k) * OC + n4));
            Bs[n4 + 0][k] = __float2half_rn(w4.x);
            Bs[n4 + 1][k] = __float2half_rn(w4.y);
            Bs[n4 + 2][k] = __float2half_rn(w4.z);
            Bs[n4 + 3][k] = __float2half_rn(w4.w);
        }
        __syncthreads();

        const int r0 = wid * 16 + g;
        #pragma unroll
        for (int ks = 0; ks < 4; ks++) {
            const int kk = ks * 16 + tid * 2;
            const unsigned a0 = *(const unsigned*)&As[r0][kk];
            const unsigned a1 = *(const unsigned*)&As[r0 + 8][kk];
            const unsigned a2 = *(const unsigned*)&As[r0][kk + 8];
            const unsigned a3 = *(const unsigned*)&As[r0 + 8][kk + 8];
            #pragma unroll
            for (int nt = 0; nt < 16; nt++) {
                const int n = nt * 8 + g;
                const unsigned b0 = *(const unsigned*)&Bs[n][kk];
                const unsigned b1 = *(const unsigned*)&Bs[n][kk + 8];
                mma16816(d[nt][0], d[nt][1], d[nt][2], d[nt][3],
                         a0, a1, a2, a3, b0, b1);
            }
        }
        __syncthreads();
    }

    // ---- epilogue: store h (fp16) + fused scores ----
    const int node0 = nbase + wid * 16 + g;
    const int node1 = node0 + 8;

    #pragma unroll
    for (int nt = 0; nt < 16; nt++) {
        const int col = nt * 8 + tid * 2;
        const __half2 h01 = __floats2half2_rn(d[nt][0], d[nt][1]);
        const __half2 h23 = __floats2half2_rn(d[nt][2], d[nt][3]);
        *(__half2*)(g_hh + (size_t)node0 * OC + col) = h01;   // padded buffer: always safe
        *(__half2*)(g_hh + (size_t)node1 * OC + col) = h23;
    }

    float ssA[4] = {0,0,0,0}, sdA[4] = {0,0,0,0};
    float ssB[4] = {0,0,0,0}, sdB[4] = {0,0,0,0};
    #pragma unroll
    for (int h = 0; h < 4; h++) {
        #pragma unroll
        for (int j = 0; j < 4; j++) {
            const int nt = h * 4 + j;
            const int off = j * 8 + tid * 2;
            const float2 as2 = __ldg((const float2*)(att + h * 64 + off));
            const float2 ad2 = __ldg((const float2*)(att + h * 64 + 32 + off));
            ssA[h] += d[nt][0] * as2.x + d[nt][1] * as2.y;
            sdA[h] += d[nt][0] * ad2.x + d[nt][1] * ad2.y;
            ssB[h] += d[nt][2] * as2.x + d[nt][3] * as2.y;
            sdB[h] += d[nt][2] * ad2.x + d[nt][3] * ad2.y;
        }
    }
    #pragma unroll
    for (int h = 0; h < 4; h++) {
        #pragma unroll
        for (int off = 1; off <= 2; off <<= 1) {
            ssA[h] += __shfl_xor_sync(0xffffffffu, ssA[h], off);
            sdA[h] += __shfl_xor_sync(0xffffffffu, sdA[h], off);
            ssB[h] += __shfl_xor_sync(0xffffffffu, ssB[h], off);
            sdB[h] += __shfl_xor_sync(0xffffffffu, sdB[h], off);
        }
    }
    if (tid == 0) {
        if (node0 < N_NODES) {
            *(float4*)(g_ssrc + (size_t)node0 * 4) = make_float4(ssA[0], ssA[1], ssA[2], ssA[3]);
            *(float4*)(g_sdst + (size_t)node0 * 4) = make_float4(sdA[0], sdA[1], sdA[2], sdA[3]);
        }
        if (node1 < N_NODES) {
            *(float4*)(g_ssrc + (size_t)node1 * 4) = make_float4(ssB[0], ssB[1], ssB[2], ssB[3]);
            *(float4*)(g_sdst + (size_t)node1 * 4) = make_float4(sdB[0], sdB[1], sdB[2], sdB[3]);
        }
    }
    // per-head global max (warp-reduced, then 4 atomics)
    const float NINF = -__int_as_float(0x7f800000);
    float mm[4];
    #pragma unroll
    for (int h = 0; h < 4; h++) {
        float a = (node0 < N_NODES) ? ssA[h] : NINF;
        float b = (node1 < N_NODES) ? ssB[h] : NINF;
        mm[h] = fmaxf(a, b);
        #pragma unroll
        for (int off = 4; off <= 16; off <<= 1)
            mm[h] = fmaxf(mm[h], __shfl_xor_sync(0xffffffffu, mm[h], off));
    }
    if (lane < 4)
        atomicMax(&g_maxss[lane], fenc(mm[lane]));
}

// ---------------- K2: degree histogram (reads dst only) --------------------
__global__ void k_hist(const void* __restrict__ ei) {
    const int e = blockIdx.x * blockDim.x + threadIdx.x;
    if (e >= E_EDGES) return;
    int dst;
    if (g_is64) dst = (int)((const long long*)ei)[E_EDGES + e];
    else        dst = ((const int*)ei)[E_EDGES + e];
    atomicAdd(&g_deg[dst], 1);
}

// ---------------- K3a/b/c: device-wide exclusive scan ------------------------
__global__ void __launch_bounds__(SCAN_BLK) k_scan_local() {
    __shared__ int ws[32];
    const int t = threadIdx.x;
    const int lane = t & 31;
    const int warp = t >> 5;
    const int i = blockIdx.x * SCAN_BLK + t;

    const int val = (i < N_NODES) ? g_deg[i] : 0;
    int v = val;
    #pragma unroll
    for (int d = 1; d < 32; d <<= 1) {
        const int u = __shfl_up_sync(0xffffffffu, v, d);
        if (lane >= d) v += u;
    }
    if (lane == 31) ws[warp] = v;
    __syncthreads();
    if (warp == 0) {
        int w = ws[lane];
        #pragma unroll
        for (int d = 1; d < 32; d <<= 1) {
            const int u = __shfl_up_sync(0xffffffffu, w, d);
            if (lane >= d) w += u;
        }
        ws[lane] = w;
    }
    __syncthreads();
    const int incl = v + (warp ? ws[warp - 1] : 0);
    if (i < N_NODES) g_off[i] = incl - val;
    if (t == SCAN_BLK - 1) g_bsum[blockIdx.x] = incl;
}

__global__ void __launch_bounds__(128) k_scan_bsum() {
    __shared__ int ws[4];
    const int t = threadIdx.x;
    const int lane = t & 31;
    const int warp = t >> 5;
    const int val = (t < N_SCAN_BLOCKS) ? g_bsum[t] : 0;
    int v = val;
    #pragma unroll
    for (int d = 1; d < 32; d <<= 1) {
        const int u = __shfl_up_sync(0xffffffffu, v, d);
        if (lane >= d) v += u;
    }
    if (lane == 31) ws[warp] = v;
    __syncthreads();
    int wpre = 0;
    #pragma unroll
    for (int w = 0; w < 4; w++) if (w < warp) wpre += ws[w];
    if (t < N_SCAN_BLOCKS) g_bpre[t] = v - val + wpre;
}

__global__ void __launch_bounds__(SCAN_BLK) k_scan_final() {
    const int i = blockIdx.x * SCAN_BLK + threadIdx.x;
    if (i < N_NODES) {
        const int o = g_off[i] + g_bpre[blockIdx.x];
        g_off[i] = o;
        g_cursor[i] = o;
    }
    if (i == 0) g_off[N_NODES] = E_EDGES;
}

// ---------------- K4: CSR position scatter (src only, 4 B) -----------------
__global__ void k_edge2(const void* __restrict__ ei) {
    const int e = blockIdx.x * blockDim.x + threadIdx.x;
    if (e >= E_EDGES) return;
    int src, dst;
    if (g_is64) {
        const long long* p = (const long long*)ei;
        src = (int)p[e]; dst = (int)p[E_EDGES + e];
    } else {
        const int* p = (const int*)ei;
        src = p[e]; dst = p[E_EDGES + e];
    }
    const int pos = atomicAdd(&g_cursor[dst], 1);
    g_csr_src[pos] = src;
}

// ---------------- K5: aggregation w/ on-the-fly softmax (1 warp/node) ------
__device__ __forceinline__ void edge_fma(int src, float sd, float bnd, int head, int c0,
                                         float4& acc, float& sumw) {
    const float ss = __ldg(g_ssrc + (size_t)src * 4 + head);
    const float w = __expf(leaky(ss + sd) - bnd);
    const uint2 r = *(const uint2*)(g_hh + (size_t)src * OC + c0);
    const float2 a = __half22float2(*(const __half2*)&r.x);
    const float2 b = __half22float2(*(const __half2*)&r.y);
    acc.x = fmaf(w, a.x, acc.x); acc.y = fmaf(w, a.y, acc.y);
    acc.z = fmaf(w, b.x, acc.z); acc.w = fmaf(w, b.y, acc.w);
    sumw += w;
}

__global__ void __launch_bounds__(256) k_aggregate(float* __restrict__ out,
                                                   const float* __restrict__ bias) {
    const int n = (blockIdx.x * blockDim.x + threadIdx.x) >> 5;
    if (n >= N_NODES) return;
    const int lane = threadIdx.x & 31;
    const int head = lane >> 3;
    const int c0 = lane * 4;

    const int beg = __ldg(g_off + n);
    const int end = __ldg(g_off + n + 1);

    const float sd = __ldg(g_sdst + (size_t)n * 4 + head);
    const float bnd = leaky(fdec(g_maxss[head]) + sd);

    float4 acc = make_float4(0.f, 0.f, 0.f, 0.f);
    float sumw = 0.f;

    int p = beg;
    for (; p + 4 <= end; p += 4) {
        const int s0 = __ldg(g_csr_src + p);
        const int s1 = __ldg(g_csr_src + p + 1);
        const int s2 = __ldg(g_csr_src + p + 2);
        const int s3 = __ldg(g_csr_src + p + 3);
        edge_fma(s0, sd, bnd, head, c0, acc, sumw);
        edge_fma(s1, sd, bnd, head, c0, acc, sumw);
        edge_fma(s2, sd, bnd, head, c0, acc, sumw);
        edge_fma(s3, sd, bnd, head, c0, acc, sumw);
    }
    for (; p < end; p++) {
        const int s0 = __ldg(g_csr_src + p);
        edge_fma(s0, sd, bnd, head, c0, acc, sumw);
    }

    const float r = 1.f / (sumw + 1e-16f);
    const float4 b4 = __ldg((const float4*)(bias + c0));
    float4 o;
    o.x = fmaf(acc.x, r, b4.x);
    o.y = fmaf(acc.y, r, b4.y);
    o.z = fmaf(acc.z, r, b4.z);
    o.w = fmaf(acc.w, r, b4.w);
    *(float4*)(out + (size_t)n * OC + c0) = o;
}

// ---------------- launch ----------------
extern "C" void kernel_launch(void* const* d_in, const int* in_sizes, int n_in,
                              void* d_out, int out_size) {
    const float* x    = (const float*)d_in[0];
    const void*  ei   = d_in[1];
    const float* W    = (const float*)d_in[2];
    const float* att  = (const float*)d_in[3];
    const float* bias = (const float*)d_in[4];
    float*       out  = (float*)d_out;

    (void)in_sizes; (void)n_in; (void)out_size;

    k_init<<<(N_NODES + 255) / 256, 256>>>((const unsigned*)ei);
    k_gemm_mma<<<GEMM_CTAS, 256>>>(x, W, att);
    k_hist<<<(E_EDGES + 255) / 256, 256>>>(ei);
    k_scan_local<<<N_SCAN_BLOCKS, SCAN_BLK>>>();
    k_scan_bsum<<<1, 128>>>();
    k_scan_final<<<N_SCAN_BLOCKS, SCAN_BLK>>>();
    k_edge2<<<(E_EDGES + 255) / 256, 256>>>(ei);
    k_aggregate<<<(N_NODES * 32 + 255) / 256, 256>>>(out, bias);
}